// round 7
// baseline (speedup 1.0000x reference)
#include <cuda_runtime.h>
#include <cstdint>

// ---------------------------------------------------------------------------
// RASP pairwise score — type-sorted, order-correct, single-wave resident.
//  R6 evidence: pair 35.4us, occ 54% (reg-limit 12 blk/SM vs 15.9 needed),
//  issue 70%, ~48 instr/body. R7: <=32 regs => 16 blk/SM single wave; body
//  slimmed (no dist clamp, 1-SEL index select); warp-shfl prep scan.
// ---------------------------------------------------------------------------

static constexpr int N_MAX   = 6144;
static constexpr int T_TYPES = 85;
static constexpr int TJ      = 128;
static constexpr int HJ      = 64;
static constexpr int BLOCK_T = 128;
static constexpr int NTILES  = N_MAX / TJ;                  // 48
static constexpr int NWORK   = NTILES * (NTILES + 1) / 2;   // 1176
static constexpr int NBLK    = NWORK * 2;                   // 2352 (~15.9/SM)
static constexpr int KSTRIDE = 85 * 85 * 21;                // 151725

__device__ float4 g_atoms[N_MAX];   // sorted coords
__device__ int4   g_meta[N_MAX];    // {res, t*21, t*1764, orig_idx}
__device__ float  g_es;             // zero-init; last block resets
__device__ unsigned int g_ticket;

// ---------------------------------------------------------------------------
// Fused prep: pack + poison + histogram + warp-shfl scan + scatter. 1 block.
__global__ __launch_bounds__(1024)
void prep_kernel(const float* __restrict__ coords,
                 const int*   __restrict__ res_ids,
                 const int*   __restrict__ types,
                 int n)
{
    __shared__ int s_hist[96];
    __shared__ int s_off[T_TYPES];
    const int tid = threadIdx.x;
    constexpr int APT = N_MAX / 1024;   // 6

    if (tid < 96) s_hist[tid] = 0;
    __syncthreads();

    float4 lc[APT];
    int    lt[APT], lr[APT];
#pragma unroll
    for (int q = 0; q < APT; q++) {
        int i = tid + q * 1024;
        float x = 0.f, y = 0.f, z = 0.f;
        int t = -1, r = 0;
        if (i < n) {
            x = coords[3 * i + 0];
            y = coords[3 * i + 1];
            z = coords[3 * i + 2];
            t = types[i];
            r = res_ids[i];
        }
        if (t < 0) {
            // Poison: spacing 32 > 20 also excludes poisoned-poisoned pairs.
            float p = 1.0e6f + 32.0f * (float)i;
            x = p; y = p; z = p;
            t = 0;
        }
        lc[q] = make_float4(x, y, z, 0.f);
        lt[q] = t; lr[q] = r;
        atomicAdd(&s_hist[t], 1);
    }
    __syncthreads();

    // Single-warp exclusive scan over 85 bins (3 x 32 shfl segments + carry).
    if (tid < 32) {
        int h0 = s_hist[tid];
        int h1 = s_hist[tid + 32];
        int h2 = s_hist[tid + 64];          // bins 85..95 are zero
        int s0 = h0, s1 = h1, s2 = h2;
#pragma unroll
        for (int o = 1; o < 32; o <<= 1) {
            int t0 = __shfl_up_sync(0xffffffffu, s0, o);
            int t1 = __shfl_up_sync(0xffffffffu, s1, o);
            int t2 = __shfl_up_sync(0xffffffffu, s2, o);
            if (tid >= o) { s0 += t0; s1 += t1; s2 += t2; }
        }
        int tot0 = __shfl_sync(0xffffffffu, s0, 31);
        int tot1 = __shfl_sync(0xffffffffu, s1, 31);
        s1 += tot0;
        s2 += tot0 + tot1;
        s_off[tid]      = s0 - h0;          // exclusive
        s_off[tid + 32] = s1 - h1;
        if (tid + 64 < T_TYPES) s_off[tid + 64] = s2 - h2;
    }
    __syncthreads();

#pragma unroll
    for (int q = 0; q < APT; q++) {
        int i = tid + q * 1024;
        int t = lt[q];
        int pos = atomicAdd(&s_off[t], 1);
        g_atoms[pos] = lc[q];
        g_meta[pos]  = make_int4(lr[q], t * 21, t * 1764, i);
    }
}

// ---------------------------------------------------------------------------
__global__ __launch_bounds__(BLOCK_T, 16)   // <=32 regs -> 16 blk/SM, 1 wave
void pair_kernel(const float* __restrict__ pot, float* __restrict__ out)
{
    // Triangular decode on blockIdx.x: bid -> (iT, jT), jT >= iT.
    const int bid = blockIdx.x;
    int iT = (int)((97.0f - sqrtf(9409.0f - 8.0f * (float)bid)) * 0.5f);
#define TRI_S(i) (((97 * (i)) - (i) * (i)) / 2)
    while (TRI_S(iT + 1) <= bid) iT++;
    while (TRI_S(iT) > bid) iT--;
    const int jT = iT + (bid - TRI_S(iT));
#undef TRI_S
    const int hbase = blockIdx.y * HJ;

    __shared__ float4 sA[HJ];
    __shared__ int4   sM[HJ];
    const int tid = threadIdx.x;
    if (tid < HJ) {
        sA[tid] = g_atoms[jT * TJ + hbase + tid];
    } else {
        sM[tid - HJ] = g_meta[jT * TJ + hbase + (tid - HJ)];
    }
    __syncthreads();

    const float4 a  = g_atoms[iT * TJ + tid];
    const int4   im = g_meta [iT * TJ + tid];
    const float xi = a.x, yi = a.y, zi = a.z;
    const int ri = im.x, ti21 = im.y, ti1764 = im.z, oi = im.w;

    float es0 = 0.f, es1 = 0.f;

    // Branchless body. Gather index always in-bounds:
    //   kk in [0,5] (max0 kept: masked pairs can have sep=0),
    //   d0i clamped to 19 so idx+1 stays in table.
    // No dist clamp: masked pairs produce a finite garbage val, killed by w=0.
    // (ti,tj) order = original-index order (pot not symmetric): one SEL.
#define PAIR_BODY(J, ES, CHECK_IJ)                                             \
    {                                                                          \
        float4 s = sA[J];                                                      \
        int4   m = sM[J];                                                      \
        float dx = xi - s.x, dy = yi - s.y, dz = zi - s.z;                     \
        float d2 = dx * dx + dy * dy + dz * dz;                                \
        float dist;                                                            \
        asm("sqrt.approx.f32 %0, %1;" : "=f"(dist) : "f"(d2));                 \
        int sepd = ri - m.x;                                                   \
        int sep  = sepd < 0 ? -sepd : sepd;                                    \
        bool ok = (sep > 2) && (dist < 20.0f);                                 \
        if (CHECK_IJ) ok = ok && (hbase + (J) > tid);                          \
        int d0i = min((int)dist, 19);                                          \
        float alpha = dist - (float)d0i;                                       \
        int kk  = min(max(sep - 1, 0), 5);                                     \
        int idx = kk * KSTRIDE + (ti21 + m.y)                                  \
                + ((oi < m.w) ? ti1764 : m.z) + d0i;                           \
        float e0 = __ldg(pot + idx);                                           \
        float e1 = __ldg(pot + idx + 1);                                       \
        float val = fmaf(alpha, e1 - e0, e0) - 2.7f;                           \
        float w = ok ? 1.0f : 0.0f;                                            \
        ES = fmaf(w, val, ES);                                                 \
    }

    if (iT != jT) {
#pragma unroll 4
        for (int j = 0; j < HJ; j += 2) {
            PAIR_BODY(j,     es0, false)
            PAIR_BODY(j + 1, es1, false)
        }
    } else {
#pragma unroll 4
        for (int j = 0; j < HJ; j += 2) {
            PAIR_BODY(j,     es0, true)
            PAIR_BODY(j + 1, es1, true)
        }
    }
#undef PAIR_BODY

    float es = es0 + es1;
#pragma unroll
    for (int o = 16; o > 0; o >>= 1)
        es += __shfl_down_sync(0xffffffffu, es, o);

    __shared__ float wes[BLOCK_T / 32];
    if ((tid & 31) == 0) wes[tid >> 5] = es;
    __syncthreads();

    if (tid == 0) {
        float e = 0.f;
#pragma unroll
        for (int w = 0; w < BLOCK_T / 32; w++) e += wes[w];

        atomicAdd(&g_es, e);
        __threadfence();
        unsigned int t = atomicAdd(&g_ticket, 1u);
        if (t == (unsigned int)(NBLK - 1)) {
            __threadfence();
            *out = *(volatile float*)&g_es;
            g_es = 0.0f;          // reset for next graph replay
            g_ticket = 0u;
        }
    }
}

// ---------------------------------------------------------------------------
extern "C" void kernel_launch(void* const* d_in, const int* in_sizes, int n_in,
                              void* d_out, int out_size)
{
    const float* coords  = (const float*)d_in[0];
    const int*   res_ids = (const int*)  d_in[1];
    const int*   types   = (const int*)  d_in[2];
    const float* pot     = (const float*)d_in[3];
    float*       out     = (float*)d_out;

    int n = in_sizes[1];
    if (n > N_MAX) n = N_MAX;

    prep_kernel<<<1, 1024>>>(coords, res_ids, types, n);

    dim3 grid(NWORK, 2);
    pair_kernel<<<grid, BLOCK_T>>>(pot, out);
}

// round 8
// speedup vs baseline: 1.0776x; 1.0776x over previous
#include <cuda_runtime.h>
#include <cstdint>

// ---------------------------------------------------------------------------
// RASP pairwise score — type-sorted, order-correct.
//  R7 evidence: pair 35.3us @ ~41 instr/body (issue-floor 22us); prep 1-block
//  = single-SM DRAM latency ~8us. R8: full-chip 3-phase prep; pair IPT=2
//  (amortized j-loads, 2x ILP), slimmer index math.
// ---------------------------------------------------------------------------

static constexpr int N_MAX   = 6144;
static constexpr int T_TYPES = 85;
static constexpr int KSTRIDE = 85 * 85 * 21;                // 151725
static constexpr int BLOCK_T = 128;
static constexpr int ITILE   = 256;                         // i per block (IPT=2)
static constexpr int JTILE   = 64;                          // j per block
static constexpr int NIT     = N_MAX / ITILE;               // 24
static constexpr int NJT     = N_MAX / JTILE;               // 96
// live blocks: sum_{iT}(96 - 4*iT) = 1200
static constexpr int NLIVE   = NIT * NJT - 4 * (NIT * (NIT - 1) / 2);

__device__ float4 g_tmp[N_MAX];     // packed, unsorted: {x,y,z, (t<<22)|(rank<<9)|r}
__device__ float4 g_atoms[N_MAX];   // sorted coords
__device__ int4   g_meta[N_MAX];    // sorted {res, t*21, t*1764, orig_idx}
__device__ int    g_hist[T_TYPES];  // zero-init; scan kernel re-zeroes per replay
__device__ int    g_base[T_TYPES];
__device__ float  g_es;             // zero-init; last pair block resets
__device__ unsigned int g_ticket;

// ---------------------------------------------------------------------------
// Phase 1 (full chip): load, poison, rank within type via atomic histogram.
__global__ void pack_kernel(const float* __restrict__ coords,
                            const int*   __restrict__ res_ids,
                            const int*   __restrict__ types,
                            int n)
{
    int i = blockIdx.x * blockDim.x + threadIdx.x;
    if (i >= N_MAX) return;

    float x = 0.f, y = 0.f, z = 0.f;
    int t = -1, r = 0;
    if (i < n) {
        x = coords[3 * i + 0];
        y = coords[3 * i + 1];
        z = coords[3 * i + 2];
        t = types[i];
        r = res_ids[i];
    }
    if (t < 0) {
        // Poison: spacing 32 > 20 also excludes poisoned-poisoned pairs.
        float p = 1.0e6f + 32.0f * (float)i;
        x = p; y = p; z = p;
        t = 0;
    }
    int rank = atomicAdd(&g_hist[t], 1);            // 13 bits
    int w = (t << 22) | (rank << 9) | r;            // 7 | 13 | 9 bits
    g_tmp[i] = make_float4(x, y, z, __int_as_float(w));
}

// ---------------------------------------------------------------------------
// Phase 2 (1 warp): exclusive scan of 85 bins -> g_base; re-zero g_hist.
__global__ void scan_kernel()
{
    int lane = threadIdx.x;                         // blockDim = 32
    int h0 = (lane < T_TYPES)      ? g_hist[lane]      : 0;
    int h1 = (lane + 32 < T_TYPES) ? g_hist[lane + 32] : 0;
    int h2 = (lane + 64 < T_TYPES) ? g_hist[lane + 64] : 0;
    int s0 = h0, s1 = h1, s2 = h2;
#pragma unroll
    for (int o = 1; o < 32; o <<= 1) {
        int t0 = __shfl_up_sync(0xffffffffu, s0, o);
        int t1 = __shfl_up_sync(0xffffffffu, s1, o);
        int t2 = __shfl_up_sync(0xffffffffu, s2, o);
        if (lane >= o) { s0 += t0; s1 += t1; s2 += t2; }
    }
    int tot0 = __shfl_sync(0xffffffffu, s0, 31);
    int tot1 = __shfl_sync(0xffffffffu, s1, 31);
    s1 += tot0;
    s2 += tot0 + tot1;
    if (lane < T_TYPES)      { g_base[lane]      = s0 - h0; g_hist[lane]      = 0; }
    if (lane + 32 < T_TYPES) { g_base[lane + 32] = s1 - h1; g_hist[lane + 32] = 0; }
    if (lane + 64 < T_TYPES) { g_base[lane + 64] = s2 - h2; g_hist[lane + 64] = 0; }
}

// ---------------------------------------------------------------------------
// Phase 3 (full chip): scatter into type-sorted order (g_tmp is L2-resident).
__global__ void scatter_kernel()
{
    int i = blockIdx.x * blockDim.x + threadIdx.x;
    if (i >= N_MAX) return;
    float4 a = g_tmp[i];
    int w = __float_as_int(a.w);
    int t    = w >> 22;
    int rank = (w >> 9) & 0x1FFF;
    int r    = w & 0x1FF;
    int pos = g_base[t] + rank;
    g_atoms[pos] = make_float4(a.x, a.y, a.z, 0.f);
    g_meta[pos]  = make_int4(r, t * 21, t * 1764, i);
}

// ---------------------------------------------------------------------------
// Pair kernel: block = 128 threads, covers ITILE=256 i (2 per thread) x 64 j.
__global__ __launch_bounds__(BLOCK_T, 9)
void pair_kernel(const float* __restrict__ pot, float* __restrict__ out)
{
    const int jF = blockIdx.x;                 // 0..95
    const int iT = blockIdx.y;                 // 0..23
    if (jF < 4 * iT) return;                   // fully below diagonal (dead)

    __shared__ float4 sA[JTILE];
    __shared__ int4   sM[JTILE];
    const int tid = threadIdx.x;
    const int jbase = jF * JTILE;
    if (tid < JTILE) sA[tid]          = g_atoms[jbase + tid];
    else             sM[tid - JTILE]  = g_meta [jbase + tid - JTILE];
    __syncthreads();

    const int i0 = iT * ITILE + tid;
    const int i1 = i0 + BLOCK_T;
    const float4 a0 = g_atoms[i0];
    const float4 a1 = g_atoms[i1];
    const int4   n0 = g_meta [i0];
    const int4   n1 = g_meta [i1];
    const float* potm1 = pot - KSTRIDE;        // kc in [1,6] re-biases

    float es0 = 0.f, es1 = 0.f;

    // Branchless body, always-in-bounds gather:
    //   kc = min(max(sep,1),6) in [1,6]; with potm1 base => k-slot 0..5.
    //   d0i clamped to 19 so idx+1 stays in the table row.
    //   (ti,tj) order = ORIGINAL-index order (pot not symmetric): 1 SEL.
    //   Masked pairs produce finite garbage val, annihilated by w=0.
#define PAIR_ONE(XI, YI, ZI, NI, ES, CHECK_IJ, IGL)                            \
    {                                                                          \
        float dx = XI - s.x, dy = YI - s.y, dz = ZI - s.z;                     \
        float d2 = dx * dx + dy * dy + dz * dz;                                \
        float dist;                                                            \
        asm("sqrt.approx.f32 %0, %1;" : "=f"(dist) : "f"(d2));                 \
        int sepd = NI.x - mm.x;                                                \
        int sep  = sepd < 0 ? -sepd : sepd;                                    \
        bool ok = (sep > 2) && (dist < 20.0f);                                 \
        if (CHECK_IJ) ok = ok && (jbase + (J) > (IGL));                        \
        int kc  = min(max(sep, 1), 6);                                         \
        int d0i = min((int)dist, 19);                                          \
        float alpha = dist - (float)d0i;                                       \
        int idx = kc * KSTRIDE + (NI.y + mm.y)                                 \
                + ((NI.w < mm.w) ? NI.z : mm.z) + d0i;                         \
        float e0 = __ldg(potm1 + idx);                                         \
        float e1 = __ldg(potm1 + idx + 1);                                     \
        float val = fmaf(alpha, e1 - e0, e0) - 2.7f;                           \
        float w = ok ? 1.0f : 0.0f;                                            \
        ES = fmaf(w, val, ES);                                                 \
    }

    const bool diag = (jF <= 4 * iT + 3);
    if (!diag) {
#pragma unroll 4
        for (int J = 0; J < JTILE; J++) {
            float4 s = sA[J];
            int4  mm = sM[J];
            PAIR_ONE(a0.x, a0.y, a0.z, n0, es0, false, i0)
            PAIR_ONE(a1.x, a1.y, a1.z, n1, es1, false, i1)
        }
    } else {
#pragma unroll 4
        for (int J = 0; J < JTILE; J++) {
            float4 s = sA[J];
            int4  mm = sM[J];
            PAIR_ONE(a0.x, a0.y, a0.z, n0, es0, true, i0)
            PAIR_ONE(a1.x, a1.y, a1.z, n1, es1, true, i1)
        }
    }
#undef PAIR_ONE

    float es = es0 + es1;
#pragma unroll
    for (int o = 16; o > 0; o >>= 1)
        es += __shfl_down_sync(0xffffffffu, es, o);

    __shared__ float wes[BLOCK_T / 32];
    if ((tid & 31) == 0) wes[tid >> 5] = es;
    __syncthreads();

    if (tid == 0) {
        float e = 0.f;
#pragma unroll
        for (int w = 0; w < BLOCK_T / 32; w++) e += wes[w];

        atomicAdd(&g_es, e);
        __threadfence();
        unsigned int t = atomicAdd(&g_ticket, 1u);
        if (t == (unsigned int)(NLIVE - 1)) {
            __threadfence();
            *out = *(volatile float*)&g_es;
            g_es = 0.0f;          // reset for next graph replay
            g_ticket = 0u;
        }
    }
}

// ---------------------------------------------------------------------------
extern "C" void kernel_launch(void* const* d_in, const int* in_sizes, int n_in,
                              void* d_out, int out_size)
{
    const float* coords  = (const float*)d_in[0];
    const int*   res_ids = (const int*)  d_in[1];
    const int*   types   = (const int*)  d_in[2];
    const float* pot     = (const float*)d_in[3];
    float*       out     = (float*)d_out;

    int n = in_sizes[1];
    if (n > N_MAX) n = N_MAX;

    pack_kernel<<<N_MAX / 128, 128>>>(coords, res_ids, types, n);
    scan_kernel<<<1, 32>>>();
    scatter_kernel<<<N_MAX / 128, 128>>>();

    dim3 grid(NJT, NIT);   // (96, 24); below-diagonal blocks exit immediately
    pair_kernel<<<grid, BLOCK_T>>>(pot, out);
}